// round 16
// baseline (speedup 1.0000x reference)
#include <cuda_runtime.h>

// NeuralBPDecoder: sparse BP, 3 launches.
// k_build (2048 scan blocks + 128 tail blocks):
//   scan H (537 MB, 8-deep uint4 batches) -> slot-major ELL adjacency;
//   tail blocks concurrently transpose llr->g_llrT/g_vT and synd->g_sT
//   (smem 32x32 tiles) and zero the sentinel rows. Counters zero at entry
//   (static init call 1; persist epilogue re-zeroes).
// k_sort: coalesced slot-major sort + sentinel pad (determinism).
// bp_persist (148 x 512, co-resident, split-line software grid barrier):
//   coalesced register hoist -> 15 x two phases -> sigmoid output.
// Warp = 4 groups x 8 lanes; group owns one node (group-strided mapping);
// lane owns a float4 batch-quad; inner loop = SHFL -> LDG.128 -> f32x2 adds.

#define NC 8192
#define NV 16384
#define NB 32
#define RD 64
#define CD 48
#define ITERS 15
#define NBLK 148
#define NTHR 512

#define B_BLOCKS 2048
#define T_BLOCKS 128
#define B_THREADS 256
#define U 8
#define FULL 0xffffffffu

// slot-major adjacency: slot j of node i at [j * N + i]
__device__ int   g_row_cnt[NC];
__device__ int   g_row_cols[RD * NC];
__device__ int   g_col_cnt[NV];
__device__ int   g_col_rows[CD * NV];
__device__ float g_vT[(NV + 1) * NB];   // beliefs, 128B rows; row NV = zeros
__device__ float g_cT[(NC + 1) * NB];   // check messages;   row NC = zeros
__device__ float g_sT[NC * NB];         // syndrome signs, node-major
__device__ float g_llrT[NV * NB];       // channel llrs, node-major

// Barrier: one word per 256B line; monotonic counter.
__device__ __align__(256) unsigned g_bar_cnt[64];
__device__ __align__(256) unsigned g_bar_gen[64];

__device__ __forceinline__ unsigned ld_acq(const unsigned* p) {
    unsigned v;
    asm volatile("ld.global.acquire.gpu.u32 %0, [%1];" : "=r"(v) : "l"(p) : "memory");
    return v;
}

__device__ __forceinline__ void grid_sync() {
    __syncthreads();
    if (threadIdx.x == 0) {
        __threadfence();
        unsigned gen = ld_acq(&g_bar_gen[0]);
        unsigned arrived = atomicAdd(&g_bar_cnt[0], 1) + 1;
        if (arrived == (gen + 1) * NBLK) {
            atomicAdd(&g_bar_gen[0], 1);
        } else {
            while (ld_acq(&g_bar_gen[0]) == gen) { }
        }
        __threadfence();
    }
    __syncthreads();
}

__device__ __forceinline__ void emit_quad(long i, uint4 h) {
    long base = i * 4;
    unsigned vals[4] = {h.x, h.y, h.z, h.w};
    #pragma unroll
    for (int k = 0; k < 4; k++) {
        if (vals[k]) {
            long e = base + k;
            int c = (int)(e >> 14);
            int v = (int)(e & (NV - 1));
            int rs = atomicAdd(&g_row_cnt[c], 1);
            if (rs < RD) g_row_cols[rs * NC + c] = v;
            int cs = atomicAdd(&g_col_cnt[v], 1);
            if (cs < CD) g_col_rows[cs * NV + v] = c;
        }
    }
}

__global__ void __launch_bounds__(B_THREADS)
k_build(const uint4* __restrict__ H4,
        const float* __restrict__ synd, const float* __restrict__ llr) {
    if (blockIdx.x >= B_BLOCKS) {
        // ---- tail blocks: smem-tiled transposes + sentinel zeroing ----
        __shared__ float s[32][33];
        int tail = blockIdx.x - B_BLOCKS;
        int tx = threadIdx.x & 31, ty = threadIdx.x >> 5;   // 32 x 8
        const int NT_L = NV / 32, NT_S = NC / 32;
        for (int t = tail; t < NT_L + NT_S; t += T_BLOCKS) {
            if (t < NT_L) {                                  // llr tile
                int v0 = t * 32;
                #pragma unroll
                for (int k = 0; k < 4; k++) {
                    int b = ty + k * 8;
                    s[b][tx] = llr[b * NV + v0 + tx];
                }
                __syncthreads();
                #pragma unroll
                for (int k = 0; k < 4; k++) {
                    int row = ty + k * 8;
                    float x = s[tx][row];
                    g_llrT[(v0 + row) * NB + tx] = x;
                    g_vT[(v0 + row) * NB + tx]   = x;
                }
            } else {                                         // synd tile
                int c0 = (t - NT_L) * 32;
                #pragma unroll
                for (int k = 0; k < 4; k++) {
                    int b = ty + k * 8;
                    s[b][tx] = synd[b * NC + c0 + tx];
                }
                __syncthreads();
                #pragma unroll
                for (int k = 0; k < 4; k++) {
                    int row = ty + k * 8;
                    g_sT[(c0 + row) * NB + tx] = 1.0f - 2.0f * s[tx][row];
                }
            }
            __syncthreads();
        }
        if (tail == 0 && threadIdx.x < NB) {                 // sentinel rows
            g_vT[NV * NB + threadIdx.x] = 0.0f;
            g_cT[NC * NB + threadIdx.x] = 0.0f;
        }
        return;
    }
    // ---- scan blocks ----
    const long n4 = (long)NC * NV / 4;
    const long stride = (long)B_BLOCKS * B_THREADS;
    long i = (long)blockIdx.x * B_THREADS + threadIdx.x;

    for (; i + (U - 1) * stride < n4; i += U * stride) {
        uint4 h[U];
        #pragma unroll
        for (int u = 0; u < U; u++)
            h[u] = __ldcs(&H4[i + u * stride]);
        #pragma unroll
        for (int u = 0; u < U; u++) {
            if (h[u].x | h[u].y | h[u].z | h[u].w)
                emit_quad(i + u * stride, h[u]);
        }
    }
    for (; i < n4; i += stride) {
        uint4 h = __ldcs(&H4[i]);
        if (h.x | h.y | h.z | h.w)
            emit_quad(i, h);
    }
}

// Slot-major sort: loads/stores coalesced across nodes.
__global__ void __launch_bounds__(256)
k_sort() {
    int i = blockIdx.x * 256 + threadIdx.x;
    int tmp[RD];
    if (i < NV) {
        int n = min(g_col_cnt[i], CD);
        g_col_cnt[i] = n;
        for (int j = 0; j < n; j++) tmp[j] = g_col_rows[j * NV + i];
        for (int j = 1; j < n; j++) {
            int key = tmp[j]; int k = j - 1;
            while (k >= 0 && tmp[k] > key) { tmp[k + 1] = tmp[k]; k--; }
            tmp[k + 1] = key;
        }
        int w = max(n, 32);
        for (int j = 0; j < w; j++)
            g_col_rows[j * NV + i] = (j < n) ? tmp[j] : NC;  // sentinel
    }
    if (i < NC) {
        int n = min(g_row_cnt[i], RD);
        g_row_cnt[i] = n;
        for (int j = 0; j < n; j++) tmp[j] = g_row_cols[j * NC + i];
        for (int j = 1; j < n; j++) {
            int key = tmp[j]; int k = j - 1;
            while (k >= 0 && tmp[k] > key) { tmp[k + 1] = tmp[k]; k--; }
            tmp[k + 1] = key;
        }
        int w = max(n, 32);
        for (int j = 0; j < w; j++)
            g_row_cols[j * NC + i] = (j < n) ? tmp[j] : NV;  // sentinel
    }
}

// packed fp32x2 add (sm_100+): a += v
__device__ __forceinline__ void padd(unsigned long long& a, unsigned long long v) {
    asm("add.rn.f32x2 %0, %1, %2;" : "=l"(a) : "l"(a), "l"(v));
}

// tanh(y) = 1 - 2/(exp(2y)+1); caller passes z = 2y.
__device__ __forceinline__ float tanh_of_half(float z) {
    return 1.0f - __fdividef(2.0f, __expf(z) + 1.0f);
}

__global__ void __launch_bounds__(NTHR, 1)
bp_persist(const float* __restrict__ wvc_p, const float* __restrict__ wcv_p,
           const float* __restrict__ damp_p, float* __restrict__ out) {
    const int tid   = blockIdx.x * NTHR + threadIdx.x;
    const int gsz   = NBLK * NTHR;
    const int wib   = threadIdx.x >> 5;
    const int lane  = threadIdx.x & 31;
    const int sub   = lane & 7;            // float4 slot (batch quad)
    const int grp   = lane >> 3;           // group in warp
    const int gbase = lane & 24;
    const int gid   = wib * 4 + grp;       // group id in block (0..63)
    const unsigned GMASK = 0xFFu << gbase;

    const float wvc  = __ldg(wvc_p);
    const float wcv  = __ldg(wcv_p);
    const float damp = __ldg(damp_p);
    const float omd  = 1.0f - damp;

    float4* __restrict__ vT4 = (float4*)g_vT;
    float4* __restrict__ cT4 = (float4*)g_cT;
    const float4* __restrict__ sT4   = (const float4*)g_sT;
    const float4* __restrict__ llrT4 = (const float4*)g_llrT;
    const ulonglong2* __restrict__ vTu = (const ulonglong2*)g_vT;
    const ulonglong2* __restrict__ cTu = (const ulonglong2*)g_cT;

    // ---- group-strided ownership + coalesced register hoist ----
    const int c    = blockIdx.x + gid * NBLK;     // this group's check
    const bool chas = (c < NC);                   // group-uniform
    int cdeg = 0, cblk = 0;
    int cidx0 = NV, cidx1 = NV, cidx2 = NV, cidx3 = NV;
    float4 csgn = make_float4(0.f, 0.f, 0.f, 0.f);
    if (chas) {
        cdeg  = g_row_cnt[c];
        cidx0 = g_row_cols[(0 * 8 + sub) * NC + c];
        cidx1 = g_row_cols[(1 * 8 + sub) * NC + c];
        cidx2 = g_row_cols[(2 * 8 + sub) * NC + c];
        cidx3 = g_row_cols[(3 * 8 + sub) * NC + c];
        csgn  = sT4[(c << 3) + sub];
        cblk  = min((cdeg + 7) >> 3, 4);
    }
    int  vvv[2], vdeg[2], vblk[2];
    int  vidx[2][4];
    bool vhas[2];
    float4 vch[2], vb[2];
    #pragma unroll
    for (int r = 0; r < 2; r++) {
        int v   = blockIdx.x + (gid + 64 * r) * NBLK;
        vhas[r] = (v < NV);                       // group-uniform
        vvv[r] = 0; vdeg[r] = 0; vblk[r] = 0;
        vidx[r][0] = vidx[r][1] = vidx[r][2] = vidx[r][3] = NC;
        vch[r] = make_float4(0.f, 0.f, 0.f, 0.f); vb[r] = vch[r];
        if (vhas[r]) {
            vvv[r]  = v;
            vdeg[r] = g_col_cnt[v];
            vidx[r][0] = g_col_rows[(0 * 8 + sub) * NV + v];
            vidx[r][1] = g_col_rows[(1 * 8 + sub) * NV + v];
            vidx[r][2] = g_col_rows[(2 * 8 + sub) * NV + v];
            vidx[r][3] = g_col_rows[(3 * 8 + sub) * NV + v];
            vch[r] = llrT4[(v << 3) + sub];
            vb[r]  = vch[r];
            vblk[r] = min((vdeg[r] + 7) >> 3, 4);
        }
    }
    // initial beliefs were published by k_build's tail (g_vT = llrT)

    // ---- BP iterations ----
    for (int it = 0; it < ITERS; it++) {
        // v -> c
        if (chas) {
            unsigned long long A0 = 0, A1 = 0, B0 = 0, B1 = 0;
            #pragma unroll
            for (int jb = 0; jb < 4; jb++) {
                if (jb >= cblk) break;                 // group-uniform branch
                int reg = (jb == 0) ? cidx0 : (jb == 1) ? cidx1
                        : (jb == 2) ? cidx2 : cidx3;
                #pragma unroll
                for (int m = 0; m < 8; m += 2) {
                    int i0 = __shfl_sync(GMASK, reg, gbase + m);
                    int i1 = __shfl_sync(GMASK, reg, gbase + m + 1);
                    ulonglong2 t0 = vTu[(i0 << 3) + sub];
                    ulonglong2 t1 = vTu[(i1 << 3) + sub];
                    padd(A0, t0.x); padd(A1, t0.y);
                    padd(B0, t1.x); padd(B1, t1.y);
                }
            }
            if (cdeg > 32) {                           // very rare tail
                for (int j = 32; j < cdeg; j++) {
                    int idx = g_row_cols[j * NC + c];
                    ulonglong2 t = vTu[(idx << 3) + sub];
                    padd(A0, t.x); padd(A1, t.y);
                }
            }
            padd(A0, B0); padd(A1, B1);
            float2 lo = *(float2*)&A0;
            float2 hi = *(float2*)&A1;
            float4 m4;
            m4.x = csgn.x * tanh_of_half(wvc * lo.x);
            m4.y = csgn.y * tanh_of_half(wvc * lo.y);
            m4.z = csgn.z * tanh_of_half(wvc * hi.x);
            m4.w = csgn.w * tanh_of_half(wvc * hi.y);
            cT4[(c << 3) + sub] = m4;
        }
        grid_sync();

        // c -> v + damped update
        #pragma unroll
        for (int r = 0; r < 2; r++) {
            if (vhas[r]) {
                unsigned long long A0 = 0, A1 = 0, B0 = 0, B1 = 0;
                #pragma unroll
                for (int jb = 0; jb < 4; jb++) {
                    if (jb >= vblk[r]) break;          // group-uniform branch
                    int reg = vidx[r][jb];
                    #pragma unroll
                    for (int m = 0; m < 8; m += 2) {
                        int i0 = __shfl_sync(GMASK, reg, gbase + m);
                        int i1 = __shfl_sync(GMASK, reg, gbase + m + 1);
                        ulonglong2 t0 = cTu[(i0 << 3) + sub];
                        ulonglong2 t1 = cTu[(i1 << 3) + sub];
                        padd(A0, t0.x); padd(A1, t0.y);
                        padd(B0, t1.x); padd(B1, t1.y);
                    }
                }
                if (vdeg[r] > 32) {                    // essentially never
                    for (int j = 32; j < vdeg[r]; j++) {
                        int idx = g_col_rows[j * NV + vvv[r]];
                        ulonglong2 t = cTu[(idx << 3) + sub];
                        padd(A0, t.x); padd(A1, t.y);
                    }
                }
                padd(A0, B0); padd(A1, B1);
                float2 lo = *(float2*)&A0;
                float2 hi = *(float2*)&A1;
                vb[r].x = damp * vb[r].x + omd * (vch[r].x + wcv * lo.x);
                vb[r].y = damp * vb[r].y + omd * (vch[r].y + wcv * lo.y);
                vb[r].z = damp * vb[r].z + omd * (vch[r].z + wcv * hi.x);
                vb[r].w = damp * vb[r].w + omd * (vch[r].w + wcv * hi.y);
                vT4[(vvv[r] << 3) + sub] = vb[r];
            }
        }
        grid_sync();
    }

    // ---- output sigmoid(-v) from registers, (b, v) order ----
    #pragma unroll
    for (int r = 0; r < 2; r++) {
        if (vhas[r]) {
            int v = vvv[r];
            out[(sub * 4 + 0) * NV + v] = __fdividef(1.0f, 1.0f + __expf(vb[r].x));
            out[(sub * 4 + 1) * NV + v] = __fdividef(1.0f, 1.0f + __expf(vb[r].y));
            out[(sub * 4 + 2) * NV + v] = __fdividef(1.0f, 1.0f + __expf(vb[r].z));
            out[(sub * 4 + 3) * NV + v] = __fdividef(1.0f, 1.0f + __expf(vb[r].w));
        }
    }

    // ---- reset state for next call (graph-replay deterministic) ----
    for (int i = tid; i < NV; i += gsz) {
        g_col_cnt[i] = 0;
        if (i < NC) g_row_cnt[i] = 0;
    }
    if (tid == 0) { g_bar_cnt[0] = 0; g_bar_gen[0] = 0; }
}

extern "C" void kernel_launch(void* const* d_in, const int* in_sizes, int n_in,
                              void* d_out, int out_size) {
    const float* synd = (const float*)d_in[0];
    const float* H    = (const float*)d_in[1];
    const float* llr  = (const float*)d_in[2];
    const float* wvc  = (const float*)d_in[3];
    const float* wcv  = (const float*)d_in[4];
    const float* damp = (const float*)d_in[5];
    float* out = (float*)d_out;

    k_build<<<B_BLOCKS + T_BLOCKS, B_THREADS>>>((const uint4*)H, synd, llr);
    k_sort<<<(NV + 255) / 256, 256>>>();
    bp_persist<<<NBLK, NTHR>>>(wvc, wcv, damp, out);
}

// round 17
// speedup vs baseline: 1.3006x; 1.3006x over previous
#include <cuda_runtime.h>

// NeuralBPDecoder: sparse BP, 3 launches.
// k_build: stream H (537 MB, 8-deep uint4 batches) -> SLOT-MAJOR staging
//          adjacency (atomics; counters zero at entry, persist re-zeroes).
// k_sort:  coalesced slot-major reads -> insertion sort -> node-major final
//          arrays via contiguous int4 stores; sentinel-pad to 32; zero
//          sentinel rows. (Determinism: fixed ascending summation order.)
// bp_persist (148 x 512, co-resident, split-line monotonic grid barrier):
//   hoist state to registers -> 15 x two phases -> sigmoid output.
// Warp = 4 groups x 8 lanes; group owns one node; lane owns a float4 batch
// quad; group-scoped loop bounds; inner loop = SHFL -> LDG.128 -> f32x2 adds.

#define NC 8192
#define NV 16384
#define NB 32
#define RD 64
#define CD 48
#define ITERS 15
#define NBLK 148
#define NTHR 512
#define WPB  (NTHR / 32)

#define B_BLOCKS 2048
#define B_THREADS 256
#define U 8
#define FULL 0xffffffffu

// staging (slot-major): slot j of node i at [j * N + i]
__device__ int   g_row_s[RD * NC];
__device__ int   g_col_s[CD * NV];
// final (node-major): what bp_persist reads
__device__ int   g_row_cnt[NC];
__device__ int   g_row_cols[NC * RD];
__device__ int   g_col_cnt[NV];
__device__ int   g_col_rows[NV * CD];
__device__ float g_vT[(NV + 1) * NB];   // beliefs, 128B rows; row NV = zeros
__device__ float g_cT[(NC + 1) * NB];   // check messages;   row NC = zeros

// Barrier: one word per 256B line; monotonic counter.
__device__ __align__(256) unsigned g_bar_cnt[64];
__device__ __align__(256) unsigned g_bar_gen[64];

__device__ __forceinline__ unsigned ld_acq(const unsigned* p) {
    unsigned v;
    asm volatile("ld.global.acquire.gpu.u32 %0, [%1];" : "=r"(v) : "l"(p) : "memory");
    return v;
}

__device__ __forceinline__ void grid_sync() {
    __syncthreads();
    if (threadIdx.x == 0) {
        __threadfence();
        unsigned gen = ld_acq(&g_bar_gen[0]);
        unsigned arrived = atomicAdd(&g_bar_cnt[0], 1) + 1;
        if (arrived == (gen + 1) * NBLK) {
            atomicAdd(&g_bar_gen[0], 1);
        } else {
            while (ld_acq(&g_bar_gen[0]) == gen) { }
        }
        __threadfence();
    }
    __syncthreads();
}

__device__ __forceinline__ void emit_quad(long i, uint4 h) {
    long base = i * 4;
    unsigned vals[4] = {h.x, h.y, h.z, h.w};
    #pragma unroll
    for (int k = 0; k < 4; k++) {
        if (vals[k]) {
            long e = base + k;
            int c = (int)(e >> 14);
            int v = (int)(e & (NV - 1));
            int rs = atomicAdd(&g_row_cnt[c], 1);
            if (rs < RD) g_row_s[rs * NC + c] = v;
            int cs = atomicAdd(&g_col_cnt[v], 1);
            if (cs < CD) g_col_s[cs * NV + v] = c;
        }
    }
}

__global__ void __launch_bounds__(B_THREADS)
k_build(const uint4* __restrict__ H4) {
    const long n4 = (long)NC * NV / 4;
    const long stride = (long)B_BLOCKS * B_THREADS;
    long i = (long)blockIdx.x * B_THREADS + threadIdx.x;

    for (; i + (U - 1) * stride < n4; i += U * stride) {
        uint4 h[U];
        #pragma unroll
        for (int u = 0; u < U; u++)
            h[u] = __ldcs(&H4[i + u * stride]);
        #pragma unroll
        for (int u = 0; u < U; u++) {
            if (h[u].x | h[u].y | h[u].z | h[u].w)
                emit_quad(i + u * stride, h[u]);
        }
    }
    for (; i < n4; i += stride) {
        uint4 h = __ldcs(&H4[i]);
        if (h.x | h.y | h.z | h.w)
            emit_quad(i, h);
    }
}

// Coalesced sort: slot-major staging in, node-major final out (int4 stores).
__global__ void __launch_bounds__(256)
k_sort() {
    int i = blockIdx.x * 256 + threadIdx.x;
    __align__(16) int tmp[RD];
    if (i < NV) {
        int n = min(g_col_cnt[i], CD);
        g_col_cnt[i] = n;
        for (int j = 0; j < n; j++) tmp[j] = g_col_s[j * NV + i];
        for (int j = 1; j < n; j++) {
            int key = tmp[j]; int k = j - 1;
            while (k >= 0 && tmp[k] > key) { tmp[k + 1] = tmp[k]; k--; }
            tmp[k + 1] = key;
        }
        for (int j = n; j < 32; j++) tmp[j] = NC;      // sentinel (zero row)
        int4* dst = (int4*)&g_col_rows[i * CD];
        #pragma unroll
        for (int j = 0; j < 8; j++) dst[j] = ((int4*)tmp)[j];
        for (int j = 32; j < n; j++) g_col_rows[i * CD + j] = tmp[j];
    }
    if (i < NC) {
        int n = min(g_row_cnt[i], RD);
        g_row_cnt[i] = n;
        for (int j = 0; j < n; j++) tmp[j] = g_row_s[j * NC + i];
        for (int j = 1; j < n; j++) {
            int key = tmp[j]; int k = j - 1;
            while (k >= 0 && tmp[k] > key) { tmp[k + 1] = tmp[k]; k--; }
            tmp[k + 1] = key;
        }
        for (int j = n; j < 32; j++) tmp[j] = NV;      // sentinel (zero row)
        int4* dst = (int4*)&g_row_cols[i * RD];
        #pragma unroll
        for (int j = 0; j < 8; j++) dst[j] = ((int4*)tmp)[j];
        for (int j = 32; j < n; j++) g_row_cols[i * RD + j] = tmp[j];
    }
    if (i < NB) {                                      // zero sentinel rows
        g_vT[NV * NB + i] = 0.0f;
        g_cT[NC * NB + i] = 0.0f;
    }
}

// packed fp32x2 add (sm_100+): a += v
__device__ __forceinline__ void padd(unsigned long long& a, unsigned long long v) {
    asm("add.rn.f32x2 %0, %1, %2;" : "=l"(a) : "l"(a), "l"(v));
}

// tanh(y) = 1 - 2/(exp(2y)+1); caller passes z = 2y.
__device__ __forceinline__ float tanh_of_half(float z) {
    return 1.0f - __fdividef(2.0f, __expf(z) + 1.0f);
}

__global__ void __launch_bounds__(NTHR, 1)
bp_persist(const float* __restrict__ synd, const float* __restrict__ llr,
           const float* __restrict__ wvc_p, const float* __restrict__ wcv_p,
           const float* __restrict__ damp_p, float* __restrict__ out) {
    const int tid   = blockIdx.x * NTHR + threadIdx.x;
    const int gsz   = NBLK * NTHR;
    const int wib   = threadIdx.x >> 5;
    const int lane  = threadIdx.x & 31;
    const int sub   = lane & 7;            // float4 slot (batch quad)
    const int grp   = lane >> 3;           // node within quad
    const int gbase = lane & 24;
    const unsigned GMASK = 0xFFu << gbase; // this group's shfl mask

    const float wvc  = __ldg(wvc_p);
    const float wcv  = __ldg(wcv_p);
    const float damp = __ldg(damp_p);
    const float omd  = 1.0f - damp;

    float4* __restrict__ vT4 = (float4*)g_vT;
    float4* __restrict__ cT4 = (float4*)g_cT;
    const ulonglong2* __restrict__ vTu = (const ulonglong2*)g_vT;
    const ulonglong2* __restrict__ cTu = (const ulonglong2*)g_cT;

    // ---- block-strided ownership + register hoist ----
    const int cq    = blockIdx.x + wib * NBLK;
    const bool chas = (cq < NC / 4);
    int c = 0, cdeg = 0, cblk = 0;
    int cidx0 = NV, cidx1 = NV, cidx2 = NV, cidx3 = NV;
    float4 csgn = make_float4(0.f, 0.f, 0.f, 0.f);
    if (chas) {
        c     = cq * 4 + grp;
        cdeg  = g_row_cnt[c];                 // group-uniform
        cidx0 = g_row_cols[c * RD + 0 * 8 + sub];
        cidx1 = g_row_cols[c * RD + 1 * 8 + sub];
        cidx2 = g_row_cols[c * RD + 2 * 8 + sub];
        cidx3 = g_row_cols[c * RD + 3 * 8 + sub];
        csgn.x = 1.0f - 2.0f * synd[(sub * 4 + 0) * NC + c];
        csgn.y = 1.0f - 2.0f * synd[(sub * 4 + 1) * NC + c];
        csgn.z = 1.0f - 2.0f * synd[(sub * 4 + 2) * NC + c];
        csgn.w = 1.0f - 2.0f * synd[(sub * 4 + 3) * NC + c];
        cblk = min((cdeg + 7) >> 3, 4);       // group-scoped bound
    }
    // vars: two block-strided rounds
    int  vvv[2], vdeg[2], vblk[2];
    int  vidx[2][4];
    bool vhas[2];
    float4 vch[2], vb[2];
    #pragma unroll
    for (int r = 0; r < 2; r++) {
        int vq  = blockIdx.x + (wib + r * WPB) * NBLK;
        vhas[r] = (vq < NV / 4);
        vvv[r] = 0; vdeg[r] = 0; vblk[r] = 0;
        vidx[r][0] = vidx[r][1] = vidx[r][2] = vidx[r][3] = NC;
        vch[r] = make_float4(0.f, 0.f, 0.f, 0.f); vb[r] = vch[r];
        if (vhas[r]) {
            int v   = vq * 4 + grp;
            vvv[r]  = v;
            vdeg[r] = g_col_cnt[v];           // group-uniform
            vidx[r][0] = g_col_rows[v * CD + 0 * 8 + sub];
            vidx[r][1] = g_col_rows[v * CD + 1 * 8 + sub];
            vidx[r][2] = g_col_rows[v * CD + 2 * 8 + sub];
            vidx[r][3] = g_col_rows[v * CD + 3 * 8 + sub];
            vch[r].x = llr[(sub * 4 + 0) * NV + v];
            vch[r].y = llr[(sub * 4 + 1) * NV + v];
            vch[r].z = llr[(sub * 4 + 2) * NV + v];
            vch[r].w = llr[(sub * 4 + 3) * NV + v];
            vb[r] = vch[r];
            vT4[(v << 3) + sub] = vb[r];      // publish initial beliefs
            vblk[r] = min((vdeg[r] + 7) >> 3, 4);
        }
    }
    grid_sync();

    // ---- BP iterations ----
    for (int it = 0; it < ITERS; it++) {
        // v -> c : group iterates only its own ceil(deg/8) blocks
        if (chas) {
            unsigned long long A0 = 0, A1 = 0, B0 = 0, B1 = 0;
            #pragma unroll
            for (int jb = 0; jb < 4; jb++) {
                if (jb >= cblk) break;                 // group-uniform branch
                int reg = (jb == 0) ? cidx0 : (jb == 1) ? cidx1
                        : (jb == 2) ? cidx2 : cidx3;
                #pragma unroll
                for (int m = 0; m < 8; m += 2) {
                    int i0 = __shfl_sync(GMASK, reg, gbase + m);
                    int i1 = __shfl_sync(GMASK, reg, gbase + m + 1);
                    ulonglong2 t0 = vTu[(i0 << 3) + sub];
                    ulonglong2 t1 = vTu[(i1 << 3) + sub];
                    padd(A0, t0.x); padd(A1, t0.y);
                    padd(B0, t1.x); padd(B1, t1.y);
                }
            }
            if (cdeg > 32) {                           // very rare tail
                for (int j = 32; j < cdeg; j++) {
                    int idx = g_row_cols[c * RD + j];
                    ulonglong2 t = vTu[(idx << 3) + sub];
                    padd(A0, t.x); padd(A1, t.y);
                }
            }
            padd(A0, B0); padd(A1, B1);
            float2 lo = *(float2*)&A0;
            float2 hi = *(float2*)&A1;
            float4 m4;
            m4.x = csgn.x * tanh_of_half(wvc * lo.x);
            m4.y = csgn.y * tanh_of_half(wvc * lo.y);
            m4.z = csgn.z * tanh_of_half(wvc * hi.x);
            m4.w = csgn.w * tanh_of_half(wvc * hi.y);
            cT4[(c << 3) + sub] = m4;
        }
        grid_sync();

        // c -> v + damped update
        #pragma unroll
        for (int r = 0; r < 2; r++) {
            if (vhas[r]) {
                unsigned long long A0 = 0, A1 = 0, B0 = 0, B1 = 0;
                #pragma unroll
                for (int jb = 0; jb < 4; jb++) {
                    if (jb >= vblk[r]) break;          // group-uniform branch
                    int reg = vidx[r][jb];
                    #pragma unroll
                    for (int m = 0; m < 8; m += 2) {
                        int i0 = __shfl_sync(GMASK, reg, gbase + m);
                        int i1 = __shfl_sync(GMASK, reg, gbase + m + 1);
                        ulonglong2 t0 = cTu[(i0 << 3) + sub];
                        ulonglong2 t1 = cTu[(i1 << 3) + sub];
                        padd(A0, t0.x); padd(A1, t0.y);
                        padd(B0, t1.x); padd(B1, t1.y);
                    }
                }
                if (vdeg[r] > 32) {                    // essentially never
                    for (int j = 32; j < vdeg[r]; j++) {
                        int idx = g_col_rows[vvv[r] * CD + j];
                        ulonglong2 t = cTu[(idx << 3) + sub];
                        padd(A0, t.x); padd(A1, t.y);
                    }
                }
                padd(A0, B0); padd(A1, B1);
                float2 lo = *(float2*)&A0;
                float2 hi = *(float2*)&A1;
                vb[r].x = damp * vb[r].x + omd * (vch[r].x + wcv * lo.x);
                vb[r].y = damp * vb[r].y + omd * (vch[r].y + wcv * lo.y);
                vb[r].z = damp * vb[r].z + omd * (vch[r].z + wcv * hi.x);
                vb[r].w = damp * vb[r].w + omd * (vch[r].w + wcv * hi.y);
                vT4[(vvv[r] << 3) + sub] = vb[r];
            }
        }
        grid_sync();
    }

    // ---- output sigmoid(-v) from registers, (b, v) order ----
    #pragma unroll
    for (int r = 0; r < 2; r++) {
        if (vhas[r]) {
            int v = vvv[r];
            out[(sub * 4 + 0) * NV + v] = __fdividef(1.0f, 1.0f + __expf(vb[r].x));
            out[(sub * 4 + 1) * NV + v] = __fdividef(1.0f, 1.0f + __expf(vb[r].y));
            out[(sub * 4 + 2) * NV + v] = __fdividef(1.0f, 1.0f + __expf(vb[r].z));
            out[(sub * 4 + 3) * NV + v] = __fdividef(1.0f, 1.0f + __expf(vb[r].w));
        }
    }

    // ---- reset state for the next call (graph-replay deterministic) ----
    for (int i = tid; i < NV; i += gsz) {
        g_col_cnt[i] = 0;
        if (i < NC) g_row_cnt[i] = 0;
    }
    if (tid == 0) { g_bar_cnt[0] = 0; g_bar_gen[0] = 0; }
}

extern "C" void kernel_launch(void* const* d_in, const int* in_sizes, int n_in,
                              void* d_out, int out_size) {
    const float* synd = (const float*)d_in[0];
    const float* H    = (const float*)d_in[1];
    const float* llr  = (const float*)d_in[2];
    const float* wvc  = (const float*)d_in[3];
    const float* wcv  = (const float*)d_in[4];
    const float* damp = (const float*)d_in[5];
    float* out = (float*)d_out;

    k_build<<<B_BLOCKS, B_THREADS>>>((const uint4*)H);
    k_sort<<<(NV + 255) / 256, 256>>>();
    bp_persist<<<NBLK, NTHR>>>(synd, llr, wvc, wcv, damp, out);
}